// round 10
// baseline (speedup 1.0000x reference)
#include <cuda_runtime.h>
#include <cuda_fp16.h>
#include <cstdint>

// ============================================================================
// EdgeTransformerLayer (B=2, N=64, D=256, H=8, DK=32, DFF=1024)
// GEMMs: mma.sync.m16n8k16 fp16 (fp32 accum) + ldmatrix, double-buffered SMEM.
// Attention: TX=4, 256 blocks (2 independent CTAs/SM), SMEM double-buffered.
// ============================================================================

namespace {
constexpr int Bb  = 2;
constexpr int Nn  = 64;
constexpr int Dd  = 256;
constexpr int Hh  = 8;
constexpr int DKk = 32;
constexpr int DFF = 1024;
constexpr int RR  = Bb * Nn * Nn;   // 8192
constexpr int SPH = 40;             // GEMM smem row stride (halfs): 80B
constexpr int BUFH = 128 * SPH;     // halfs per GEMM smem buffer
constexpr int TX  = 4;              // attention x-tile per CTA
}

// ---- device-global scratch (no allocation allowed) --------------------------
__device__ float  g_h     [RR * Dd];
__device__ float  g_proj  [RR * DFF];  // [0,256)=lk*scale [256,512)=rk [512,768)=lv [768,1024)=rv
__device__ float  g_att   [RR * Dd];
__device__ float  g_hres  [RR * Dd];
__device__ float  g_h2    [RR * Dd];
__device__ float  g_ffn   [RR * DFF];
__device__ __half g_Wh_qkv[DFF * Dd];  // [1024,256] fp16, Wlk pre-scaled
__device__ __half g_Wh_o  [Dd * Dd];
__device__ __half g_Wh_1  [DFF * Dd];
__device__ __half g_Wh_2  [Dd * DFF];
__device__ unsigned char g_maskT[Bb * Nn * Nn * Nn];  // [b][a][y][x]

// ============================================================================
// helpers
// ============================================================================
__device__ __forceinline__ uint32_t smem_u32(const void* p) {
    uint32_t a;
    asm("{ .reg .u64 t; cvta.to.shared.u64 t, %1; cvt.u32.u64 %0, t; }" : "=r"(a) : "l"(p));
    return a;
}

__device__ __forceinline__ void mma_f16(float c[4],
                                        uint32_t a0, uint32_t a1, uint32_t a2, uint32_t a3,
                                        uint32_t b0, uint32_t b1) {
    asm volatile(
        "mma.sync.aligned.m16n8k16.row.col.f32.f16.f16.f32 "
        "{%0,%1,%2,%3}, {%4,%5,%6,%7}, {%8,%9}, {%0,%1,%2,%3};"
        : "+f"(c[0]), "+f"(c[1]), "+f"(c[2]), "+f"(c[3])
        : "r"(a0), "r"(a1), "r"(a2), "r"(a3), "r"(b0), "r"(b1));
}

__device__ __forceinline__ void ldsm_x4(uint32_t r[4], uint32_t addr) {
    asm volatile("ldmatrix.sync.aligned.m8n8.x4.shared.b16 {%0,%1,%2,%3}, [%4];"
                 : "=r"(r[0]), "=r"(r[1]), "=r"(r[2]), "=r"(r[3]) : "r"(addr));
}
__device__ __forceinline__ void ldsm_x2(uint32_t r[2], uint32_t addr) {
    asm volatile("ldmatrix.sync.aligned.m8n8.x2.shared.b16 {%0,%1}, [%2];"
                 : "=r"(r[0]), "=r"(r[1]) : "r"(addr));
}

__device__ __forceinline__ uint32_t h2u(__half2 h) {
    uint32_t u; asm("mov.b32 %0, %1;" : "=r"(u) : "r"(*(uint32_t*)&h)); return u;
}

// ---- packed f32x2 ------------------------------------------------------------
typedef unsigned long long u64;
__device__ __forceinline__ u64 pk2(float lo, float hi) {
    u64 r; asm("mov.b64 %0, {%1,%2};" : "=l"(r) : "f"(lo), "f"(hi)); return r;
}
__device__ __forceinline__ void upk2(u64 v, float& lo, float& hi) {
    asm("mov.b64 {%0,%1}, %2;" : "=f"(lo), "=f"(hi) : "l"(v));
}
__device__ __forceinline__ u64 mul2(u64 a, u64 b) {
    u64 d; asm("mul.rn.f32x2 %0, %1, %2;" : "=l"(d) : "l"(a), "l"(b)); return d;
}
__device__ __forceinline__ u64 fma2(u64 a, u64 b, u64 c) {
    u64 d; asm("fma.rn.f32x2 %0, %1, %2, %3;" : "=l"(d) : "l"(a), "l"(b), "l"(c)); return d;
}

// ============================================================================
// prep: weight transpose -> [N,K] fp16 (Wlk pre-scaled) + mask transpose
// ============================================================================
__device__ __forceinline__ __half* trh_dst(int which) {
    switch (which) {
        case 0: return g_Wh_qkv;
        case 1: return g_Wh_qkv + 256 * 256;
        case 2: return g_Wh_qkv + 512 * 256;
        case 3: return g_Wh_qkv + 768 * 256;
        case 4: return g_Wh_o;
        case 5: return g_Wh_1;
        default: return g_Wh_2;
    }
}

__global__ __launch_bounds__(256) void k_prep(const float* __restrict__ Wlk,
                                              const float* __restrict__ Wrk,
                                              const float* __restrict__ Wlv,
                                              const float* __restrict__ Wrv,
                                              const float* __restrict__ Wo,
                                              const float* __restrict__ W1,
                                              const float* __restrict__ W2,
                                              const unsigned char* __restrict__ mask)
{
    const int id = blockIdx.x;
    if (id >= 832) {
        const int g = (id - 832) * 256 + threadIdx.x;
        const int x  = g & 63;
        const int yy = (g >> 6) & 63;
        const int a  = (g >> 12) & 63;
        const int bb = g >> 18;
        g_maskT[g] = mask[(((bb * 64 + x) * 64 + a) * 64) + yy];
        return;
    }

    __shared__ float tile[32][33];
    const float* src;
    __half* dst;
    float scale = 1.0f;
    int K, N, n0, k0;
    if (id < 320) {
        const int w = id >> 6;
        const int tl = id & 63;
        src = (w == 0) ? Wlk : (w == 1) ? Wrk : (w == 2) ? Wlv : (w == 3) ? Wrv : Wo;
        dst = trh_dst(w);
        if (w == 0) scale = 0.17677669529663687f;   // 1/sqrt(32)
        K = 256; N = 256;
        n0 = (tl & 7) * 32; k0 = (tl >> 3) * 32;
    } else if (id < 576) {
        const int tl = id - 320;
        src = W1; dst = g_Wh_1; K = 256; N = 1024;
        n0 = (tl & 31) * 32; k0 = (tl >> 5) * 32;
    } else {
        const int tl = id - 576;
        src = W2; dst = g_Wh_2; K = 1024; N = 256;
        n0 = (tl & 7) * 32; k0 = (tl >> 3) * 32;
    }
    const int tx = threadIdx.x & 31;
    const int ty = threadIdx.x >> 5;
#pragma unroll
    for (int r = ty; r < 32; r += 8)
        tile[r][tx] = src[(size_t)(k0 + r) * N + n0 + tx];
    __syncthreads();
#pragma unroll
    for (int r = ty; r < 32; r += 8)
        dst[(size_t)(n0 + r) * K + k0 + tx] = __float2half_rn(tile[tx][r] * scale);
}

// ============================================================================
// LayerNorm: warp per row (8 rows / 256-thread block)
// ============================================================================
__device__ __forceinline__ void ln_body(const float* __restrict__ in,
                                        const float* __restrict__ gam,
                                        const float* __restrict__ bet,
                                        float* __restrict__ out)
{
    const int row  = blockIdx.x * 8 + (threadIdx.x >> 5);
    const int lane = threadIdx.x & 31;
    const float* rp = in + (size_t)row * Dd + lane * 8;
    const float4 v0 = *(const float4*)rp;
    const float4 v1 = *(const float4*)(rp + 4);
    float s  = v0.x + v0.y + v0.z + v0.w + v1.x + v1.y + v1.z + v1.w;
    float s2 = v0.x*v0.x + v0.y*v0.y + v0.z*v0.z + v0.w*v0.w
             + v1.x*v1.x + v1.y*v1.y + v1.z*v1.z + v1.w*v1.w;
#pragma unroll
    for (int o = 16; o; o >>= 1) {
        s  += __shfl_xor_sync(0xffffffffu, s,  o);
        s2 += __shfl_xor_sync(0xffffffffu, s2, o);
    }
    const float mean = s * (1.0f / Dd);
    const float var  = s2 * (1.0f / Dd) - mean * mean;
    const float inv  = rsqrtf(var + 1e-5f);
    const float4 g0 = *(const float4*)(gam + lane * 8);
    const float4 g1 = *(const float4*)(gam + lane * 8 + 4);
    const float4 b0 = *(const float4*)(bet + lane * 8);
    const float4 b1 = *(const float4*)(bet + lane * 8 + 4);
    float4 o0, o1;
    o0.x = (v0.x - mean) * inv * g0.x + b0.x;
    o0.y = (v0.y - mean) * inv * g0.y + b0.y;
    o0.z = (v0.z - mean) * inv * g0.z + b0.z;
    o0.w = (v0.w - mean) * inv * g0.w + b0.w;
    o1.x = (v1.x - mean) * inv * g1.x + b1.x;
    o1.y = (v1.y - mean) * inv * g1.y + b1.y;
    o1.z = (v1.z - mean) * inv * g1.z + b1.z;
    o1.w = (v1.w - mean) * inv * g1.w + b1.w;
    float* op = out + (size_t)row * Dd + lane * 8;
    *(float4*)op       = o0;
    *(float4*)(op + 4) = o1;
}

__global__ __launch_bounds__(256) void ln1_kernel(const float* __restrict__ x,
                                                  const float* __restrict__ g1,
                                                  const float* __restrict__ be1)
{ ln_body(x, g1, be1, g_h); }

__global__ __launch_bounds__(256) void ln2_kernel(const float* __restrict__ g2,
                                                  const float* __restrict__ be2)
{ ln_body(g_hres, g2, be2, g_h2); }

// ============================================================================
// fp16 mma GEMM: C[M,NC] = A[M,K] @ Wh^T, Wh [NC,K] fp16 row-major.
// CTA 128x128, 8 warps (2x4), warp tile 64x32. K chunks of 32 (2 k16 steps).
// Double-buffered SMEM. launch_bounds(256,2) -> 2 CTAs/SM.
// ============================================================================
template <int K, int NC, int EPI>
__device__ __forceinline__ void gemm_mma(const float* __restrict__ A,
                                         const __half* __restrict__ Wh,
                                         const float* __restrict__ Cadd,
                                         const float* __restrict__ bias,
                                         float* __restrict__ C)
{
    constexpr int NCH = K / 32;
    __shared__ __half As[2][BUFH];
    __shared__ __half Bs[2][BUFH];
    constexpr uint32_t BUFBYTES = BUFH * 2;

    const int t    = threadIdx.x;
    const int lane = t & 31;
    const int wid  = t >> 5;
    const int gr   = lane >> 2;
    const int tig  = lane & 3;
    const int wm   = (wid & 1) * 64;
    const int wn   = (wid >> 1) * 32;

    const int bm = blockIdx.y * 128;
    const int bn = blockIdx.x * 128;

    const uint32_t a_base = smem_u32(As) +
        ((wm + (lane & 15)) * SPH + ((lane >> 4) & 1) * 8) * 2;
    const uint32_t b_base = smem_u32(Bs) +
        ((wn + (lane & 7)) * SPH + ((lane >> 3) & 1) * 8) * 2;

    const int lrow = t >> 1;
    const int lko  = (t & 1) * 16;
    const float4* Ag  = (const float4*)(A + (size_t)(bm + lrow) * K + lko);
    const uint4*  Bgh = (const uint4*)(Wh + (size_t)(bn + lrow) * K);
    const int     bgi = (t & 1) * 2;

    float4 pa[4];
    uint4  pb0, pb1;
#pragma unroll
    for (int i = 0; i < 4; i++) pa[i] = Ag[i];
    pb0 = Bgh[bgi];
    pb1 = Bgh[bgi + 1];

    float acc[4][4][4];
#pragma unroll
    for (int im = 0; im < 4; im++)
#pragma unroll
        for (int in = 0; in < 4; in++)
#pragma unroll
            for (int j = 0; j < 4; j++) acc[im][in][j] = 0.f;

    {
        uint32_t q[8];
#pragma unroll
        for (int i = 0; i < 4; i++) {
            q[2*i]   = h2u(__floats2half2_rn(pa[i].x, pa[i].y));
            q[2*i+1] = h2u(__floats2half2_rn(pa[i].z, pa[i].w));
        }
        __half* asw = &As[0][lrow * SPH + lko];
        *(uint4*)asw       = make_uint4(q[0], q[1], q[2], q[3]);
        *(uint4*)(asw + 8) = make_uint4(q[4], q[5], q[6], q[7]);
        __half* bsw = &Bs[0][lrow * SPH + lko];
        *(uint4*)bsw       = pb0;
        *(uint4*)(bsw + 8) = pb1;
    }
    __syncthreads();

    for (int c = 0; c < NCH; c++) {
        const int buf = c & 1;

        if (c + 1 < NCH) {
#pragma unroll
            for (int i = 0; i < 4; i++) pa[i] = Ag[(c + 1) * 8 + i];
            pb0 = Bgh[bgi + (c + 1) * 4];
            pb1 = Bgh[bgi + (c + 1) * 4 + 1];
        }

        const uint32_t a_addr = a_base + buf * BUFBYTES;
        const uint32_t b_addr = b_base + buf * BUFBYTES;
#pragma unroll
        for (int ks = 0; ks < 2; ks++) {
            uint32_t af[4][4], bf[4][2];
#pragma unroll
            for (int im = 0; im < 4; im++)
                ldsm_x4(af[im], a_addr + (uint32_t)(im * 16 * SPH * 2 + ks * 32));
#pragma unroll
            for (int in = 0; in < 4; in++)
                ldsm_x2(bf[in], b_addr + (uint32_t)(in * 8 * SPH * 2 + ks * 32));
#pragma unroll
            for (int im = 0; im < 4; im++)
#pragma unroll
                for (int in = 0; in < 4; in++)
                    mma_f16(acc[im][in], af[im][0], af[im][1], af[im][2], af[im][3],
                            bf[in][0], bf[in][1]);
        }

        if (c + 1 < NCH) {
            const int nb = buf ^ 1;
            uint32_t q[8];
#pragma unroll
            for (int i = 0; i < 4; i++) {
                q[2*i]   = h2u(__floats2half2_rn(pa[i].x, pa[i].y));
                q[2*i+1] = h2u(__floats2half2_rn(pa[i].z, pa[i].w));
            }
            __half* asw = &As[nb][lrow * SPH + lko];
            *(uint4*)asw       = make_uint4(q[0], q[1], q[2], q[3]);
            *(uint4*)(asw + 8) = make_uint4(q[4], q[5], q[6], q[7]);
            __half* bsw = &Bs[nb][lrow * SPH + lko];
            *(uint4*)bsw       = pb0;
            *(uint4*)(bsw + 8) = pb1;
            __syncthreads();
        }
    }

#pragma unroll
    for (int im = 0; im < 4; im++) {
        const int r0 = bm + wm + im * 16 + gr;
#pragma unroll
        for (int in = 0; in < 4; in++) {
            const int col = bn + wn + in * 8 + 2 * tig;
            float2 v0 = make_float2(acc[im][in][0], acc[im][in][1]);
            float2 v1 = make_float2(acc[im][in][2], acc[im][in][3]);
            if (EPI == 2 || EPI == 3) {
                const float2 bb = *(const float2*)&bias[col];
                v0.x += bb.x; v0.y += bb.y;
                v1.x += bb.x; v1.y += bb.y;
            }
            if (EPI == 2) {
                v0.x = fmaxf(v0.x, 0.f); v0.y = fmaxf(v0.y, 0.f);
                v1.x = fmaxf(v1.x, 0.f); v1.y = fmaxf(v1.y, 0.f);
            }
            if (EPI == 1 || EPI == 3) {
                const float2 c0 = *(const float2*)&Cadd[(size_t)r0 * NC + col];
                const float2 c1 = *(const float2*)&Cadd[(size_t)(r0 + 8) * NC + col];
                v0.x += c0.x; v0.y += c0.y;
                v1.x += c1.x; v1.y += c1.y;
            }
            *(float2*)&C[(size_t)r0 * NC + col]       = v0;
            *(float2*)&C[(size_t)(r0 + 8) * NC + col] = v1;
        }
    }
}

__global__ __launch_bounds__(256, 2) void k_proj_tc()
{ gemm_mma<Dd, DFF, 0>(g_h, g_Wh_qkv, nullptr, nullptr, g_proj); }

__global__ __launch_bounds__(256, 2) void k_wo_tc()
{ gemm_mma<Dd, Dd, 1>(g_att, g_Wh_o, g_h, nullptr, g_hres); }

__global__ __launch_bounds__(256, 2) void k_ffn1_tc(const float* __restrict__ b1)
{ gemm_mma<Dd, DFF, 2>(g_h2, g_Wh_1, nullptr, b1, g_ffn); }

__global__ __launch_bounds__(256, 2) void k_ffn2_tc(const float* __restrict__ b2,
                                                    float* __restrict__ out)
{ gemm_mma<DFF, Dd, 3>(g_ffn, g_Wh_2, g_h2, b2, out); }

// ============================================================================
// Triangle attention v7 — TX=4, 256 threads, 256 blocks (2 indep CTAs/SM).
// SMEM rk/rv + lk/lv double-buffered; register prefetch; 1 barrier/step.
// Thread owns (y = t>>2, dq = t&3); 4 x per thread; no-max softmax; f32x2.
// ============================================================================
__global__ __launch_bounds__(256) void attn7_kernel()
{
    const int xt = blockIdx.x;      // 0..15
    const int hh = blockIdx.y;
    const int b  = blockIdx.z;
    const int t  = threadIdx.x;
    const int y  = t >> 2;
    const int dq = t & 3;
    const int x0 = xt * TX;

    __shared__ float rk_s[2][Nn][36];
    __shared__ float rv_s[2][Nn][36];
    __shared__ float lk_s[2][TX][36];
    __shared__ float lv_s[2][TX][36];

    // rk/rv loader: rows t>>3 and t>>3+32, col (t&7)*4
    const int r0c = t >> 3;
    const int r1c = r0c + 32;
    const int c4  = (t & 7) * 4;
    // lk/lv loader: t<32 -> xr = t>>3 (0..3), lc4 = (t&7)*4
    const int xr  = t >> 3;
    const int lc4 = (t & 7) * 4;

    float4 prk0, prk1, prv0, prv1, plk, plv;
    uint32_t pmN, pmC;

    // ---- prefetch a = 0 ----
    {
        const int baseR = (b * Nn * Nn) * DFF + hh * DKk;
        prk0 = *(const float4*)&g_proj[baseR + r0c * DFF + 256 + c4];
        prv0 = *(const float4*)&g_proj[baseR + r0c * DFF + 768 + c4];
        prk1 = *(const float4*)&g_proj[baseR + r1c * DFF + 256 + c4];
        prv1 = *(const float4*)&g_proj[baseR + r1c * DFF + 768 + c4];
        if (t < 32) {
            const int baseL = ((b * Nn + x0 + xr) * Nn) * DFF + hh * DKk;
            plk = *(const float4*)&g_proj[baseL + lc4];
            plv = *(const float4*)&g_proj[baseL + 512 + lc4];
        }
        pmN = *(const uint32_t*)&g_maskT[((b * Nn) * Nn + y) * 64 + x0];
    }
    *(float4*)&rk_s[0][r0c][c4] = prk0;
    *(float4*)&rv_s[0][r0c][c4] = prv0;
    *(float4*)&rk_s[0][r1c][c4] = prk1;
    *(float4*)&rv_s[0][r1c][c4] = prv1;
    if (t < 32) {
        *(float4*)&lk_s[0][xr][lc4] = plk;
        *(float4*)&lv_s[0][xr][lc4] = plv;
    }
    __syncthreads();

    u64 acc[TX][4];
    float l[TX];
#pragma unroll
    for (int xx = 0; xx < TX; xx++) {
        l[xx] = 0.f;
#pragma unroll
        for (int j = 0; j < 4; j++) acc[xx][j] = 0ull;
    }

    for (int a = 0; a < Nn; a++) {
        const int buf = a & 1;

        pmC = pmN;
        if (a + 1 < Nn) {   // prefetch a+1 (overlaps compute)
            const int baseR = ((b * Nn + (a + 1)) * Nn) * DFF + hh * DKk;
            prk0 = *(const float4*)&g_proj[baseR + r0c * DFF + 256 + c4];
            prv0 = *(const float4*)&g_proj[baseR + r0c * DFF + 768 + c4];
            prk1 = *(const float4*)&g_proj[baseR + r1c * DFF + 256 + c4];
            prv1 = *(const float4*)&g_proj[baseR + r1c * DFF + 768 + c4];
            if (t < 32) {
                const int baseL = ((b * Nn + x0 + xr) * Nn + (a + 1)) * DFF + hh * DKk;
                plk = *(const float4*)&g_proj[baseL + lc4];
                plv = *(const float4*)&g_proj[baseL + 512 + lc4];
            }
            pmN = *(const uint32_t*)&g_maskT[((b * Nn + (a + 1)) * Nn + y) * 64 + x0];
        }

        // ---- compute step a ----
        const ulonglong2 rka = *(const ulonglong2*)&rk_s[buf][y][dq * 8];
        const ulonglong2 rkb = *(const ulonglong2*)&rk_s[buf][y][dq * 8 + 4];
        const ulonglong2 rva = *(const ulonglong2*)&rv_s[buf][y][dq * 8];
        const ulonglong2 rvb = *(const ulonglong2*)&rv_s[buf][y][dq * 8 + 4];

#pragma unroll
        for (int xx = 0; xx < TX; xx++) {
            const ulonglong2 lka = *(const ulonglong2*)&lk_s[buf][xx][dq * 8];
            const ulonglong2 lkb = *(const ulonglong2*)&lk_s[buf][xx][dq * 8 + 4];
            u64 s2 = mul2(lka.x, rka.x);
            s2 = fma2(lka.y, rka.y, s2);
            s2 = fma2(lkb.x, rkb.x, s2);
            s2 = fma2(lkb.y, rkb.y, s2);
            float lo, hi;
            upk2(s2, lo, hi);
            float part = lo + hi;
            part += __shfl_xor_sync(0xffffffffu, part, 1);
            part += __shfl_xor_sync(0xffffffffu, part, 2);
            const float sc = ((pmC >> (xx * 8)) & 0xffu) ? -1e9f : part;
            const float p  = __expf(sc);
            l[xx] += p;
            const u64 pp = pk2(p, p);
            const ulonglong2 lva = *(const ulonglong2*)&lv_s[buf][xx][dq * 8];
            const ulonglong2 lvb = *(const ulonglong2*)&lv_s[buf][xx][dq * 8 + 4];
            acc[xx][0] = fma2(mul2(lva.x, rva.x), pp, acc[xx][0]);
            acc[xx][1] = fma2(mul2(lva.y, rva.y), pp, acc[xx][1]);
            acc[xx][2] = fma2(mul2(lvb.x, rvb.x), pp, acc[xx][2]);
            acc[xx][3] = fma2(mul2(lvb.y, rvb.y), pp, acc[xx][3]);
        }

        // ---- store prefetched a+1 into the other buffer ----
        if (a + 1 < Nn) {
            const int nb = buf ^ 1;
            *(float4*)&rk_s[nb][r0c][c4] = prk0;
            *(float4*)&rv_s[nb][r0c][c4] = prv0;
            *(float4*)&rk_s[nb][r1c][c4] = prk1;
            *(float4*)&rv_s[nb][r1c][c4] = prv1;
            if (t < 32) {
                *(float4*)&lk_s[nb][xr][lc4] = plk;
                *(float4*)&lv_s[nb][xr][lc4] = plv;
            }
            __syncthreads();
        }
    }

#pragma unroll
    for (int xx = 0; xx < TX; xx++) {
        const float inv = 1.0f / l[xx];
        const int ob = ((b * Nn + x0 + xx) * Nn + y) * Dd + hh * DKk + dq * 8;
        float a0, a1, a2, a3, a4, a5, a6, a7;
        upk2(acc[xx][0], a0, a1);
        upk2(acc[xx][1], a2, a3);
        upk2(acc[xx][2], a4, a5);
        upk2(acc[xx][3], a6, a7);
        float4 v0, v1;
        v0.x = a0 * inv; v0.y = a1 * inv; v0.z = a2 * inv; v0.w = a3 * inv;
        v1.x = a4 * inv; v1.y = a5 * inv; v1.z = a6 * inv; v1.w = a7 * inv;
        *(float4*)&g_att[ob]     = v0;
        *(float4*)&g_att[ob + 4] = v1;
    }
}

// ============================================================================
// launch
// ============================================================================
extern "C" void kernel_launch(void* const* d_in, const int* in_sizes, int n_in,
                              void* d_out, int out_size)
{
    const float*         x    = (const float*)d_in[0];
    const unsigned char* mask = (const unsigned char*)d_in[1];
    const float*         Wlk  = (const float*)d_in[2];
    const float*         Wrk  = (const float*)d_in[3];
    const float*         Wlv  = (const float*)d_in[4];
    const float*         Wrv  = (const float*)d_in[5];
    const float*         Wo   = (const float*)d_in[6];
    const float*         W1   = (const float*)d_in[7];
    const float*         b1   = (const float*)d_in[8];
    const float*         W2   = (const float*)d_in[9];
    const float*         b2   = (const float*)d_in[10];
    const float*         g1   = (const float*)d_in[11];
    const float*         be1  = (const float*)d_in[12];
    const float*         g2   = (const float*)d_in[13];
    const float*         be2  = (const float*)d_in[14];
    float* out = (float*)d_out;

    k_prep<<<2880, 256>>>(Wlk, Wrk, Wlv, Wrv, Wo, W1, W2, mask);
    ln1_kernel<<<RR / 8, 256>>>(x, g1, be1);
    k_proj_tc<<<dim3(DFF / 128, RR / 128), 256>>>();
    attn7_kernel<<<dim3(Nn / TX, Hh, Bb), 256>>>();
    k_wo_tc<<<dim3(Dd / 128, RR / 128), 256>>>();
    ln2_kernel<<<RR / 8, 256>>>(g2, be2);
    k_ffn1_tc<<<dim3(DFF / 128, RR / 128), 256>>>(b1);
    k_ffn2_tc<<<dim3(Dd / 128, RR / 128), 256>>>(b2, out);
}

// round 11
// speedup vs baseline: 1.0722x; 1.0722x over previous
#include <cuda_runtime.h>
#include <cuda_fp16.h>
#include <cstdint>

// ============================================================================
// EdgeTransformerLayer (B=2, N=64, D=256, H=8, DK=32, DFF=1024)
// GEMMs: mma.sync.m16n8k16 fp16 (fp32 accum) + ldmatrix, double-buffered SMEM.
// Attention: TX=8, y-split (32 rows/CTA, 128 thr, 256 CTAs -> 2 CTAs/SM).
// ============================================================================

namespace {
constexpr int Bb  = 2;
constexpr int Nn  = 64;
constexpr int Dd  = 256;
constexpr int Hh  = 8;
constexpr int DKk = 32;
constexpr int DFF = 1024;
constexpr int RR  = Bb * Nn * Nn;   // 8192
constexpr int SPH = 40;             // GEMM smem row stride (halfs): 80B
constexpr int BUFH = 128 * SPH;     // halfs per GEMM smem buffer
constexpr int TX  = 8;              // attention x-tile per CTA
}

// ---- device-global scratch (no allocation allowed) --------------------------
__device__ float  g_h     [RR * Dd];
__device__ float  g_proj  [RR * DFF];  // [0,256)=lk*scale [256,512)=rk [512,768)=lv [768,1024)=rv
__device__ float  g_att   [RR * Dd];
__device__ float  g_hres  [RR * Dd];
__device__ float  g_h2    [RR * Dd];
__device__ float  g_ffn   [RR * DFF];
__device__ __half g_Wh_qkv[DFF * Dd];  // [1024,256] fp16, Wlk pre-scaled
__device__ __half g_Wh_o  [Dd * Dd];
__device__ __half g_Wh_1  [DFF * Dd];
__device__ __half g_Wh_2  [Dd * DFF];
__device__ unsigned char g_maskT[Bb * Nn * Nn * Nn];  // [b][a][y][x]

// ============================================================================
// helpers
// ============================================================================
__device__ __forceinline__ uint32_t smem_u32(const void* p) {
    uint32_t a;
    asm("{ .reg .u64 t; cvta.to.shared.u64 t, %1; cvt.u32.u64 %0, t; }" : "=r"(a) : "l"(p));
    return a;
}

__device__ __forceinline__ void mma_f16(float c[4],
                                        uint32_t a0, uint32_t a1, uint32_t a2, uint32_t a3,
                                        uint32_t b0, uint32_t b1) {
    asm volatile(
        "mma.sync.aligned.m16n8k16.row.col.f32.f16.f16.f32 "
        "{%0,%1,%2,%3}, {%4,%5,%6,%7}, {%8,%9}, {%0,%1,%2,%3};"
        : "+f"(c[0]), "+f"(c[1]), "+f"(c[2]), "+f"(c[3])
        : "r"(a0), "r"(a1), "r"(a2), "r"(a3), "r"(b0), "r"(b1));
}

__device__ __forceinline__ void ldsm_x4(uint32_t r[4], uint32_t addr) {
    asm volatile("ldmatrix.sync.aligned.m8n8.x4.shared.b16 {%0,%1,%2,%3}, [%4];"
                 : "=r"(r[0]), "=r"(r[1]), "=r"(r[2]), "=r"(r[3]) : "r"(addr));
}
__device__ __forceinline__ void ldsm_x2(uint32_t r[2], uint32_t addr) {
    asm volatile("ldmatrix.sync.aligned.m8n8.x2.shared.b16 {%0,%1}, [%2];"
                 : "=r"(r[0]), "=r"(r[1]) : "r"(addr));
}

__device__ __forceinline__ uint32_t h2u(__half2 h) {
    uint32_t u; asm("mov.b32 %0, %1;" : "=r"(u) : "r"(*(uint32_t*)&h)); return u;
}

// ---- packed f32x2 ------------------------------------------------------------
typedef unsigned long long u64;
__device__ __forceinline__ u64 pk2(float lo, float hi) {
    u64 r; asm("mov.b64 %0, {%1,%2};" : "=l"(r) : "f"(lo), "f"(hi)); return r;
}
__device__ __forceinline__ void upk2(u64 v, float& lo, float& hi) {
    asm("mov.b64 {%0,%1}, %2;" : "=f"(lo), "=f"(hi) : "l"(v));
}
__device__ __forceinline__ u64 mul2(u64 a, u64 b) {
    u64 d; asm("mul.rn.f32x2 %0, %1, %2;" : "=l"(d) : "l"(a), "l"(b)); return d;
}
__device__ __forceinline__ u64 fma2(u64 a, u64 b, u64 c) {
    u64 d; asm("fma.rn.f32x2 %0, %1, %2, %3;" : "=l"(d) : "l"(a), "l"(b), "l"(c)); return d;
}

// ============================================================================
// prep: weight transpose -> [N,K] fp16 (Wlk pre-scaled) + mask transpose
// ============================================================================
__device__ __forceinline__ __half* trh_dst(int which) {
    switch (which) {
        case 0: return g_Wh_qkv;
        case 1: return g_Wh_qkv + 256 * 256;
        case 2: return g_Wh_qkv + 512 * 256;
        case 3: return g_Wh_qkv + 768 * 256;
        case 4: return g_Wh_o;
        case 5: return g_Wh_1;
        default: return g_Wh_2;
    }
}

__global__ __launch_bounds__(256) void k_prep(const float* __restrict__ Wlk,
                                              const float* __restrict__ Wrk,
                                              const float* __restrict__ Wlv,
                                              const float* __restrict__ Wrv,
                                              const float* __restrict__ Wo,
                                              const float* __restrict__ W1,
                                              const float* __restrict__ W2,
                                              const unsigned char* __restrict__ mask)
{
    const int id = blockIdx.x;
    if (id >= 832) {
        const int g = (id - 832) * 256 + threadIdx.x;
        const int x  = g & 63;
        const int yy = (g >> 6) & 63;
        const int a  = (g >> 12) & 63;
        const int bb = g >> 18;
        g_maskT[g] = mask[(((bb * 64 + x) * 64 + a) * 64) + yy];
        return;
    }

    __shared__ float tile[32][33];
    const float* src;
    __half* dst;
    float scale = 1.0f;
    int K, N, n0, k0;
    if (id < 320) {
        const int w = id >> 6;
        const int tl = id & 63;
        src = (w == 0) ? Wlk : (w == 1) ? Wrk : (w == 2) ? Wlv : (w == 3) ? Wrv : Wo;
        dst = trh_dst(w);
        if (w == 0) scale = 0.17677669529663687f;   // 1/sqrt(32)
        K = 256; N = 256;
        n0 = (tl & 7) * 32; k0 = (tl >> 3) * 32;
    } else if (id < 576) {
        const int tl = id - 320;
        src = W1; dst = g_Wh_1; K = 256; N = 1024;
        n0 = (tl & 31) * 32; k0 = (tl >> 5) * 32;
    } else {
        const int tl = id - 576;
        src = W2; dst = g_Wh_2; K = 1024; N = 256;
        n0 = (tl & 7) * 32; k0 = (tl >> 3) * 32;
    }
    const int tx = threadIdx.x & 31;
    const int ty = threadIdx.x >> 5;
#pragma unroll
    for (int r = ty; r < 32; r += 8)
        tile[r][tx] = src[(size_t)(k0 + r) * N + n0 + tx];
    __syncthreads();
#pragma unroll
    for (int r = ty; r < 32; r += 8)
        dst[(size_t)(n0 + r) * K + k0 + tx] = __float2half_rn(tile[tx][r] * scale);
}

// ============================================================================
// LayerNorm: warp per row (8 rows / 256-thread block)
// ============================================================================
__device__ __forceinline__ void ln_body(const float* __restrict__ in,
                                        const float* __restrict__ gam,
                                        const float* __restrict__ bet,
                                        float* __restrict__ out)
{
    const int row  = blockIdx.x * 8 + (threadIdx.x >> 5);
    const int lane = threadIdx.x & 31;
    const float* rp = in + (size_t)row * Dd + lane * 8;
    const float4 v0 = *(const float4*)rp;
    const float4 v1 = *(const float4*)(rp + 4);
    float s  = v0.x + v0.y + v0.z + v0.w + v1.x + v1.y + v1.z + v1.w;
    float s2 = v0.x*v0.x + v0.y*v0.y + v0.z*v0.z + v0.w*v0.w
             + v1.x*v1.x + v1.y*v1.y + v1.z*v1.z + v1.w*v1.w;
#pragma unroll
    for (int o = 16; o; o >>= 1) {
        s  += __shfl_xor_sync(0xffffffffu, s,  o);
        s2 += __shfl_xor_sync(0xffffffffu, s2, o);
    }
    const float mean = s * (1.0f / Dd);
    const float var  = s2 * (1.0f / Dd) - mean * mean;
    const float inv  = rsqrtf(var + 1e-5f);
    const float4 g0 = *(const float4*)(gam + lane * 8);
    const float4 g1 = *(const float4*)(gam + lane * 8 + 4);
    const float4 b0 = *(const float4*)(bet + lane * 8);
    const float4 b1 = *(const float4*)(bet + lane * 8 + 4);
    float4 o0, o1;
    o0.x = (v0.x - mean) * inv * g0.x + b0.x;
    o0.y = (v0.y - mean) * inv * g0.y + b0.y;
    o0.z = (v0.z - mean) * inv * g0.z + b0.z;
    o0.w = (v0.w - mean) * inv * g0.w + b0.w;
    o1.x = (v1.x - mean) * inv * g1.x + b1.x;
    o1.y = (v1.y - mean) * inv * g1.y + b1.y;
    o1.z = (v1.z - mean) * inv * g1.z + b1.z;
    o1.w = (v1.w - mean) * inv * g1.w + b1.w;
    float* op = out + (size_t)row * Dd + lane * 8;
    *(float4*)op       = o0;
    *(float4*)(op + 4) = o1;
}

__global__ __launch_bounds__(256) void ln1_kernel(const float* __restrict__ x,
                                                  const float* __restrict__ g1,
                                                  const float* __restrict__ be1)
{ ln_body(x, g1, be1, g_h); }

__global__ __launch_bounds__(256) void ln2_kernel(const float* __restrict__ g2,
                                                  const float* __restrict__ be2)
{ ln_body(g_hres, g2, be2, g_h2); }

// ============================================================================
// fp16 mma GEMM: C[M,NC] = A[M,K] @ Wh^T, Wh [NC,K] fp16 row-major.
// CTA 128x128, 8 warps (2x4), warp tile 64x32. K chunks of 32 (2 k16 steps).
// Double-buffered SMEM. launch_bounds(256,2) -> 2 CTAs/SM.
// ============================================================================
template <int K, int NC, int EPI>
__device__ __forceinline__ void gemm_mma(const float* __restrict__ A,
                                         const __half* __restrict__ Wh,
                                         const float* __restrict__ Cadd,
                                         const float* __restrict__ bias,
                                         float* __restrict__ C)
{
    constexpr int NCH = K / 32;
    __shared__ __half As[2][BUFH];
    __shared__ __half Bs[2][BUFH];
    constexpr uint32_t BUFBYTES = BUFH * 2;

    const int t    = threadIdx.x;
    const int lane = t & 31;
    const int wid  = t >> 5;
    const int gr   = lane >> 2;
    const int tig  = lane & 3;
    const int wm   = (wid & 1) * 64;
    const int wn   = (wid >> 1) * 32;

    const int bm = blockIdx.y * 128;
    const int bn = blockIdx.x * 128;

    const uint32_t a_base = smem_u32(As) +
        ((wm + (lane & 15)) * SPH + ((lane >> 4) & 1) * 8) * 2;
    const uint32_t b_base = smem_u32(Bs) +
        ((wn + (lane & 7)) * SPH + ((lane >> 3) & 1) * 8) * 2;

    const int lrow = t >> 1;
    const int lko  = (t & 1) * 16;
    const float4* Ag  = (const float4*)(A + (size_t)(bm + lrow) * K + lko);
    const uint4*  Bgh = (const uint4*)(Wh + (size_t)(bn + lrow) * K);
    const int     bgi = (t & 1) * 2;

    float4 pa[4];
    uint4  pb0, pb1;
#pragma unroll
    for (int i = 0; i < 4; i++) pa[i] = Ag[i];
    pb0 = Bgh[bgi];
    pb1 = Bgh[bgi + 1];

    float acc[4][4][4];
#pragma unroll
    for (int im = 0; im < 4; im++)
#pragma unroll
        for (int in = 0; in < 4; in++)
#pragma unroll
            for (int j = 0; j < 4; j++) acc[im][in][j] = 0.f;

    {
        uint32_t q[8];
#pragma unroll
        for (int i = 0; i < 4; i++) {
            q[2*i]   = h2u(__floats2half2_rn(pa[i].x, pa[i].y));
            q[2*i+1] = h2u(__floats2half2_rn(pa[i].z, pa[i].w));
        }
        __half* asw = &As[0][lrow * SPH + lko];
        *(uint4*)asw       = make_uint4(q[0], q[1], q[2], q[3]);
        *(uint4*)(asw + 8) = make_uint4(q[4], q[5], q[6], q[7]);
        __half* bsw = &Bs[0][lrow * SPH + lko];
        *(uint4*)bsw       = pb0;
        *(uint4*)(bsw + 8) = pb1;
    }
    __syncthreads();

    for (int c = 0; c < NCH; c++) {
        const int buf = c & 1;

        if (c + 1 < NCH) {
#pragma unroll
            for (int i = 0; i < 4; i++) pa[i] = Ag[(c + 1) * 8 + i];
            pb0 = Bgh[bgi + (c + 1) * 4];
            pb1 = Bgh[bgi + (c + 1) * 4 + 1];
        }

        const uint32_t a_addr = a_base + buf * BUFBYTES;
        const uint32_t b_addr = b_base + buf * BUFBYTES;
#pragma unroll
        for (int ks = 0; ks < 2; ks++) {
            uint32_t af[4][4], bf[4][2];
#pragma unroll
            for (int im = 0; im < 4; im++)
                ldsm_x4(af[im], a_addr + (uint32_t)(im * 16 * SPH * 2 + ks * 32));
#pragma unroll
            for (int in = 0; in < 4; in++)
                ldsm_x2(bf[in], b_addr + (uint32_t)(in * 8 * SPH * 2 + ks * 32));
#pragma unroll
            for (int im = 0; im < 4; im++)
#pragma unroll
                for (int in = 0; in < 4; in++)
                    mma_f16(acc[im][in], af[im][0], af[im][1], af[im][2], af[im][3],
                            bf[in][0], bf[in][1]);
        }

        if (c + 1 < NCH) {
            const int nb = buf ^ 1;
            uint32_t q[8];
#pragma unroll
            for (int i = 0; i < 4; i++) {
                q[2*i]   = h2u(__floats2half2_rn(pa[i].x, pa[i].y));
                q[2*i+1] = h2u(__floats2half2_rn(pa[i].z, pa[i].w));
            }
            __half* asw = &As[nb][lrow * SPH + lko];
            *(uint4*)asw       = make_uint4(q[0], q[1], q[2], q[3]);
            *(uint4*)(asw + 8) = make_uint4(q[4], q[5], q[6], q[7]);
            __half* bsw = &Bs[nb][lrow * SPH + lko];
            *(uint4*)bsw       = pb0;
            *(uint4*)(bsw + 8) = pb1;
            __syncthreads();
        }
    }

#pragma unroll
    for (int im = 0; im < 4; im++) {
        const int r0 = bm + wm + im * 16 + gr;
#pragma unroll
        for (int in = 0; in < 4; in++) {
            const int col = bn + wn + in * 8 + 2 * tig;
            float2 v0 = make_float2(acc[im][in][0], acc[im][in][1]);
            float2 v1 = make_float2(acc[im][in][2], acc[im][in][3]);
            if (EPI == 2 || EPI == 3) {
                const float2 bb = *(const float2*)&bias[col];
                v0.x += bb.x; v0.y += bb.y;
                v1.x += bb.x; v1.y += bb.y;
            }
            if (EPI == 2) {
                v0.x = fmaxf(v0.x, 0.f); v0.y = fmaxf(v0.y, 0.f);
                v1.x = fmaxf(v1.x, 0.f); v1.y = fmaxf(v1.y, 0.f);
            }
            if (EPI == 1 || EPI == 3) {
                const float2 c0 = *(const float2*)&Cadd[(size_t)r0 * NC + col];
                const float2 c1 = *(const float2*)&Cadd[(size_t)(r0 + 8) * NC + col];
                v0.x += c0.x; v0.y += c0.y;
                v1.x += c1.x; v1.y += c1.y;
            }
            *(float2*)&C[(size_t)r0 * NC + col]       = v0;
            *(float2*)&C[(size_t)(r0 + 8) * NC + col] = v1;
        }
    }
}

__global__ __launch_bounds__(256, 2) void k_proj_tc()
{ gemm_mma<Dd, DFF, 0>(g_h, g_Wh_qkv, nullptr, nullptr, g_proj); }

__global__ __launch_bounds__(256, 2) void k_wo_tc()
{ gemm_mma<Dd, Dd, 1>(g_att, g_Wh_o, g_h, nullptr, g_hres); }

__global__ __launch_bounds__(256, 2) void k_ffn1_tc(const float* __restrict__ b1)
{ gemm_mma<Dd, DFF, 2>(g_h2, g_Wh_1, nullptr, b1, g_ffn); }

__global__ __launch_bounds__(256, 2) void k_ffn2_tc(const float* __restrict__ b2,
                                                    float* __restrict__ out)
{ gemm_mma<DFF, Dd, 3>(g_ffn, g_Wh_2, g_h2, b2, out); }

// ============================================================================
// Triangle attention v8 — TX=8, y-split: each CTA owns 32 y-rows, 128 threads.
// Grid (16, 8, 2) = 256 CTAs -> 2 independent CTAs/SM. rk/rv bytes per work
// unchanged vs TX=8/full-y (they scale with y-extent); overlap doubled.
// Thread owns (y = y0 + t>>2, dq = t&3); 8 x per thread; no-max softmax; f32x2.
// ============================================================================
__global__ __launch_bounds__(128) void attn8_kernel()
{
    const int bx = blockIdx.x;       // 0..15
    const int xt = bx >> 1;          // 0..7
    const int yh = bx & 1;           // y-half
    const int hh = blockIdx.y;
    const int b  = blockIdx.z;
    const int t  = threadIdx.x;      // 0..127
    const int yl = t >> 2;           // local y 0..31
    const int dq = t & 3;
    const int x0 = xt * TX;
    const int y0 = yh * 32;
    const int y  = y0 + yl;

    __shared__ float rk_s[2][32][36];
    __shared__ float rv_s[2][32][36];
    __shared__ float lk_s[2][TX][36];
    __shared__ float lv_s[2][TX][36];

    // rk/rv loader: rows y0 + (t>>3) and +16; col (t&7)*4
    const int r0c = t >> 3;          // 0..15
    const int r1c = r0c + 16;
    const int c4  = (t & 7) * 4;
    // lk/lv loader: t<64 -> xr = t>>3 (0..7), lc4 = (t&7)*4
    const int xr  = t >> 3;
    const int lc4 = c4;

    float4 prk0, prk1, prv0, prv1, plk, plv;
    u64 pmN, pmC;

    // ---- prefetch a = 0 ----
    {
        const int baseR = (b * Nn * Nn) * DFF + hh * DKk;
        prk0 = *(const float4*)&g_proj[baseR + (y0 + r0c) * DFF + 256 + c4];
        prv0 = *(const float4*)&g_proj[baseR + (y0 + r0c) * DFF + 768 + c4];
        prk1 = *(const float4*)&g_proj[baseR + (y0 + r1c) * DFF + 256 + c4];
        prv1 = *(const float4*)&g_proj[baseR + (y0 + r1c) * DFF + 768 + c4];
        if (t < 64) {
            const int baseL = ((b * Nn + x0 + xr) * Nn) * DFF + hh * DKk;
            plk = *(const float4*)&g_proj[baseL + lc4];
            plv = *(const float4*)&g_proj[baseL + 512 + lc4];
        }
        pmN = *(const u64*)&g_maskT[((b * Nn) * Nn + y) * 64 + x0];
    }
    *(float4*)&rk_s[0][r0c][c4] = prk0;
    *(float4*)&rv_s[0][r0c][c4] = prv0;
    *(float4*)&rk_s[0][r1c][c4] = prk1;
    *(float4*)&rv_s[0][r1c][c4] = prv1;
    if (t < 64) {
        *(float4*)&lk_s[0][xr][lc4] = plk;
        *(float4*)&lv_s[0][xr][lc4] = plv;
    }
    __syncthreads();

    u64 acc[TX][4];
    float l[TX];
#pragma unroll
    for (int xx = 0; xx < TX; xx++) {
        l[xx] = 0.f;
#pragma unroll
        for (int j = 0; j < 4; j++) acc[xx][j] = 0ull;
    }

    for (int a = 0; a < Nn; a++) {
        const int buf = a & 1;

        pmC = pmN;
        if (a + 1 < Nn) {   // prefetch a+1 (overlaps compute)
            const int baseR = ((b * Nn + (a + 1)) * Nn) * DFF + hh * DKk;
            prk0 = *(const float4*)&g_proj[baseR + (y0 + r0c) * DFF + 256 + c4];
            prv0 = *(const float4*)&g_proj[baseR + (y0 + r0c) * DFF + 768 + c4];
            prk1 = *(const float4*)&g_proj[baseR + (y0 + r1c) * DFF + 256 + c4];
            prv1 = *(const float4*)&g_proj[baseR + (y0 + r1c) * DFF + 768 + c4];
            if (t < 64) {
                const int baseL = ((b * Nn + x0 + xr) * Nn + (a + 1)) * DFF + hh * DKk;
                plk = *(const float4*)&g_proj[baseL + lc4];
                plv = *(const float4*)&g_proj[baseL + 512 + lc4];
            }
            pmN = *(const u64*)&g_maskT[((b * Nn + (a + 1)) * Nn + y) * 64 + x0];
        }

        // ---- compute step a ----
        const ulonglong2 rka = *(const ulonglong2*)&rk_s[buf][yl][dq * 8];
        const ulonglong2 rkb = *(const ulonglong2*)&rk_s[buf][yl][dq * 8 + 4];
        const ulonglong2 rva = *(const ulonglong2*)&rv_s[buf][yl][dq * 8];
        const ulonglong2 rvb = *(const ulonglong2*)&rv_s[buf][yl][dq * 8 + 4];

#pragma unroll
        for (int xx = 0; xx < TX; xx++) {
            const ulonglong2 lka = *(const ulonglong2*)&lk_s[buf][xx][dq * 8];
            const ulonglong2 lkb = *(const ulonglong2*)&lk_s[buf][xx][dq * 8 + 4];
            u64 s2 = mul2(lka.x, rka.x);
            s2 = fma2(lka.y, rka.y, s2);
            s2 = fma2(lkb.x, rkb.x, s2);
            s2 = fma2(lkb.y, rkb.y, s2);
            float lo, hi;
            upk2(s2, lo, hi);
            float part = lo + hi;
            part += __shfl_xor_sync(0xffffffffu, part, 1);
            part += __shfl_xor_sync(0xffffffffu, part, 2);
            const float sc = ((pmC >> (xx * 8)) & 0xffull) ? -1e9f : part;
            const float p  = __expf(sc);
            l[xx] += p;
            const u64 pp = pk2(p, p);
            const ulonglong2 lva = *(const ulonglong2*)&lv_s[buf][xx][dq * 8];
            const ulonglong2 lvb = *(const ulonglong2*)&lv_s[buf][xx][dq * 8 + 4];
            acc[xx][0] = fma2(mul2(lva.x, rva.x), pp, acc[xx][0]);
            acc[xx][1] = fma2(mul2(lva.y, rva.y), pp, acc[xx][1]);
            acc[xx][2] = fma2(mul2(lvb.x, rvb.x), pp, acc[xx][2]);
            acc[xx][3] = fma2(mul2(lvb.y, rvb.y), pp, acc[xx][3]);
        }

        // ---- store prefetched a+1 into the other buffer ----
        if (a + 1 < Nn) {
            const int nb = buf ^ 1;
            *(float4*)&rk_s[nb][r0c][c4] = prk0;
            *(float4*)&rv_s[nb][r0c][c4] = prv0;
            *(float4*)&rk_s[nb][r1c][c4] = prk1;
            *(float4*)&rv_s[nb][r1c][c4] = prv1;
            if (t < 64) {
                *(float4*)&lk_s[nb][xr][lc4] = plk;
                *(float4*)&lv_s[nb][xr][lc4] = plv;
            }
            __syncthreads();
        }
    }

#pragma unroll
    for (int xx = 0; xx < TX; xx++) {
        const float inv = 1.0f / l[xx];
        const int ob = ((b * Nn + x0 + xx) * Nn + y) * Dd + hh * DKk + dq * 8;
        float a0, a1, a2, a3, a4, a5, a6, a7;
        upk2(acc[xx][0], a0, a1);
        upk2(acc[xx][1], a2, a3);
        upk2(acc[xx][2], a4, a5);
        upk2(acc[xx][3], a6, a7);
        float4 v0, v1;
        v0.x = a0 * inv; v0.y = a1 * inv; v0.z = a2 * inv; v0.w = a3 * inv;
        v1.x = a4 * inv; v1.y = a5 * inv; v1.z = a6 * inv; v1.w = a7 * inv;
        *(float4*)&g_att[ob]     = v0;
        *(float4*)&g_att[ob + 4] = v1;
    }
}

// ============================================================================
// launch
// ============================================================================
extern "C" void kernel_launch(void* const* d_in, const int* in_sizes, int n_in,
                              void* d_out, int out_size)
{
    const float*         x    = (const float*)d_in[0];
    const unsigned char* mask = (const unsigned char*)d_in[1];
    const float*         Wlk  = (const float*)d_in[2];
    const float*         Wrk  = (const float*)d_in[3];
    const float*         Wlv  = (const float*)d_in[4];
    const float*         Wrv  = (const float*)d_in[5];
    const float*         Wo   = (const float*)d_in[6];
    const float*         W1   = (const float*)d_in[7];
    const float*         b1   = (const float*)d_in[8];
    const float*         W2   = (const float*)d_in[9];
    const float*         b2   = (const float*)d_in[10];
    const float*         g1   = (const float*)d_in[11];
    const float*         be1  = (const float*)d_in[12];
    const float*         g2   = (const float*)d_in[13];
    const float*         be2  = (const float*)d_in[14];
    float* out = (float*)d_out;

    k_prep<<<2880, 256>>>(Wlk, Wrk, Wlv, Wrv, Wo, W1, W2, mask);
    ln1_kernel<<<RR / 8, 256>>>(x, g1, be1);
    k_proj_tc<<<dim3(DFF / 128, RR / 128), 256>>>();
    attn8_kernel<<<dim3(16, Hh, Bb), 128>>>();
    k_wo_tc<<<dim3(Dd / 128, RR / 128), 256>>>();
    ln2_kernel<<<RR / 8, 256>>>(g2, be2);
    k_ffn1_tc<<<dim3(DFF / 128, RR / 128), 256>>>(b1);
    k_ffn2_tc<<<dim3(Dd / 128, RR / 128), 256>>>(b2, out);
}

// round 12
// speedup vs baseline: 1.1452x; 1.0681x over previous
#include <cuda_runtime.h>
#include <cuda_fp16.h>
#include <cstdint>

// ============================================================================
// EdgeTransformerLayer (B=2, N=64, D=256, H=8, DK=32, DFF=1024)
// GEMMs: mma.sync.m16n8k16 fp16, BOTH operands pre-stored fp16 (pure-copy
// staging). Scratch g_att/g_ffn/g_hh/g_h2h in fp16 (same roundings as before,
// moved to producers). Attention: TX=8 y-split (round-11 winner) + fp16 out.
// ============================================================================

namespace {
constexpr int Bb  = 2;
constexpr int Nn  = 64;
constexpr int Dd  = 256;
constexpr int Hh  = 8;
constexpr int DKk = 32;
constexpr int DFF = 1024;
constexpr int RR  = Bb * Nn * Nn;   // 8192
constexpr int SPH = 40;             // GEMM smem row stride (halfs): 80B
constexpr int BUFH = 128 * SPH;     // halfs per GEMM smem buffer
constexpr int TX  = 8;              // attention x-tile per CTA
}

// ---- device-global scratch (no allocation allowed) --------------------------
__device__ float  g_h     [RR * Dd];   // LN1 out fp32 (wo residual)
__device__ __half g_hh    [RR * Dd];   // LN1 out fp16 (proj A)
__device__ float  g_proj  [RR * DFF];  // [0,256)=lk*scale [256,512)=rk [512,768)=lv [768,1024)=rv
__device__ __half g_att   [RR * Dd];   // attn out fp16 (wo A)
__device__ float  g_hres  [RR * Dd];
__device__ float  g_h2    [RR * Dd];   // LN2 out fp32 (ffn2 residual)
__device__ __half g_h2h   [RR * Dd];   // LN2 out fp16 (ffn1 A)
__device__ __half g_ffn   [RR * DFF];  // relu out fp16 (ffn2 A)
__device__ __half g_Wh_qkv[DFF * Dd];  // [1024,256] fp16, Wlk pre-scaled
__device__ __half g_Wh_o  [Dd * Dd];
__device__ __half g_Wh_1  [DFF * Dd];
__device__ __half g_Wh_2  [Dd * DFF];
__device__ unsigned char g_maskT[Bb * Nn * Nn * Nn];  // [b][a][y][x]

// ============================================================================
// helpers
// ============================================================================
__device__ __forceinline__ uint32_t smem_u32(const void* p) {
    uint32_t a;
    asm("{ .reg .u64 t; cvta.to.shared.u64 t, %1; cvt.u32.u64 %0, t; }" : "=r"(a) : "l"(p));
    return a;
}

__device__ __forceinline__ void mma_f16(float c[4],
                                        uint32_t a0, uint32_t a1, uint32_t a2, uint32_t a3,
                                        uint32_t b0, uint32_t b1) {
    asm volatile(
        "mma.sync.aligned.m16n8k16.row.col.f32.f16.f16.f32 "
        "{%0,%1,%2,%3}, {%4,%5,%6,%7}, {%8,%9}, {%0,%1,%2,%3};"
        : "+f"(c[0]), "+f"(c[1]), "+f"(c[2]), "+f"(c[3])
        : "r"(a0), "r"(a1), "r"(a2), "r"(a3), "r"(b0), "r"(b1));
}

__device__ __forceinline__ void ldsm_x4(uint32_t r[4], uint32_t addr) {
    asm volatile("ldmatrix.sync.aligned.m8n8.x4.shared.b16 {%0,%1,%2,%3}, [%4];"
                 : "=r"(r[0]), "=r"(r[1]), "=r"(r[2]), "=r"(r[3]) : "r"(addr));
}
__device__ __forceinline__ void ldsm_x2(uint32_t r[2], uint32_t addr) {
    asm volatile("ldmatrix.sync.aligned.m8n8.x2.shared.b16 {%0,%1}, [%2];"
                 : "=r"(r[0]), "=r"(r[1]) : "r"(addr));
}

__device__ __forceinline__ uint32_t h2u(__half2 h) {
    uint32_t u; asm("mov.b32 %0, %1;" : "=r"(u) : "r"(*(uint32_t*)&h)); return u;
}

// ---- packed f32x2 ------------------------------------------------------------
typedef unsigned long long u64;
__device__ __forceinline__ u64 pk2(float lo, float hi) {
    u64 r; asm("mov.b64 %0, {%1,%2};" : "=l"(r) : "f"(lo), "f"(hi)); return r;
}
__device__ __forceinline__ void upk2(u64 v, float& lo, float& hi) {
    asm("mov.b64 {%0,%1}, %2;" : "=f"(lo), "=f"(hi) : "l"(v));
}
__device__ __forceinline__ u64 mul2(u64 a, u64 b) {
    u64 d; asm("mul.rn.f32x2 %0, %1, %2;" : "=l"(d) : "l"(a), "l"(b)); return d;
}
__device__ __forceinline__ u64 fma2(u64 a, u64 b, u64 c) {
    u64 d; asm("fma.rn.f32x2 %0, %1, %2, %3;" : "=l"(d) : "l"(a), "l"(b), "l"(c)); return d;
}

// ============================================================================
// prep: weight transpose -> [N,K] fp16 (Wlk pre-scaled) + mask transpose
// ============================================================================
__device__ __forceinline__ __half* trh_dst(int which) {
    switch (which) {
        case 0: return g_Wh_qkv;
        case 1: return g_Wh_qkv + 256 * 256;
        case 2: return g_Wh_qkv + 512 * 256;
        case 3: return g_Wh_qkv + 768 * 256;
        case 4: return g_Wh_o;
        case 5: return g_Wh_1;
        default: return g_Wh_2;
    }
}

__global__ __launch_bounds__(256) void k_prep(const float* __restrict__ Wlk,
                                              const float* __restrict__ Wrk,
                                              const float* __restrict__ Wlv,
                                              const float* __restrict__ Wrv,
                                              const float* __restrict__ Wo,
                                              const float* __restrict__ W1,
                                              const float* __restrict__ W2,
                                              const unsigned char* __restrict__ mask)
{
    const int id = blockIdx.x;
    if (id >= 832) {
        const int g = (id - 832) * 256 + threadIdx.x;
        const int x  = g & 63;
        const int yy = (g >> 6) & 63;
        const int a  = (g >> 12) & 63;
        const int bb = g >> 18;
        g_maskT[g] = mask[(((bb * 64 + x) * 64 + a) * 64) + yy];
        return;
    }

    __shared__ float tile[32][33];
    const float* src;
    __half* dst;
    float scale = 1.0f;
    int K, N, n0, k0;
    if (id < 320) {
        const int w = id >> 6;
        const int tl = id & 63;
        src = (w == 0) ? Wlk : (w == 1) ? Wrk : (w == 2) ? Wlv : (w == 3) ? Wrv : Wo;
        dst = trh_dst(w);
        if (w == 0) scale = 0.17677669529663687f;   // 1/sqrt(32)
        K = 256; N = 256;
        n0 = (tl & 7) * 32; k0 = (tl >> 3) * 32;
    } else if (id < 576) {
        const int tl = id - 320;
        src = W1; dst = g_Wh_1; K = 256; N = 1024;
        n0 = (tl & 31) * 32; k0 = (tl >> 5) * 32;
    } else {
        const int tl = id - 576;
        src = W2; dst = g_Wh_2; K = 1024; N = 256;
        n0 = (tl & 7) * 32; k0 = (tl >> 3) * 32;
    }
    const int tx = threadIdx.x & 31;
    const int ty = threadIdx.x >> 5;
#pragma unroll
    for (int r = ty; r < 32; r += 8)
        tile[r][tx] = src[(size_t)(k0 + r) * N + n0 + tx];
    __syncthreads();
#pragma unroll
    for (int r = ty; r < 32; r += 8)
        dst[(size_t)(n0 + r) * K + k0 + tx] = __float2half_rn(tile[tx][r] * scale);
}

// ============================================================================
// LayerNorm: warp per row; writes fp32 (residual path) + fp16 (GEMM A path)
// ============================================================================
__device__ __forceinline__ void ln_body(const float* __restrict__ in,
                                        const float* __restrict__ gam,
                                        const float* __restrict__ bet,
                                        float* __restrict__ out,
                                        __half* __restrict__ outh)
{
    const int row  = blockIdx.x * 8 + (threadIdx.x >> 5);
    const int lane = threadIdx.x & 31;
    const float* rp = in + (size_t)row * Dd + lane * 8;
    const float4 v0 = *(const float4*)rp;
    const float4 v1 = *(const float4*)(rp + 4);
    float s  = v0.x + v0.y + v0.z + v0.w + v1.x + v1.y + v1.z + v1.w;
    float s2 = v0.x*v0.x + v0.y*v0.y + v0.z*v0.z + v0.w*v0.w
             + v1.x*v1.x + v1.y*v1.y + v1.z*v1.z + v1.w*v1.w;
#pragma unroll
    for (int o = 16; o; o >>= 1) {
        s  += __shfl_xor_sync(0xffffffffu, s,  o);
        s2 += __shfl_xor_sync(0xffffffffu, s2, o);
    }
    const float mean = s * (1.0f / Dd);
    const float var  = s2 * (1.0f / Dd) - mean * mean;
    const float inv  = rsqrtf(var + 1e-5f);
    const float4 g0 = *(const float4*)(gam + lane * 8);
    const float4 g1 = *(const float4*)(gam + lane * 8 + 4);
    const float4 b0 = *(const float4*)(bet + lane * 8);
    const float4 b1 = *(const float4*)(bet + lane * 8 + 4);
    float4 o0, o1;
    o0.x = (v0.x - mean) * inv * g0.x + b0.x;
    o0.y = (v0.y - mean) * inv * g0.y + b0.y;
    o0.z = (v0.z - mean) * inv * g0.z + b0.z;
    o0.w = (v0.w - mean) * inv * g0.w + b0.w;
    o1.x = (v1.x - mean) * inv * g1.x + b1.x;
    o1.y = (v1.y - mean) * inv * g1.y + b1.y;
    o1.z = (v1.z - mean) * inv * g1.z + b1.z;
    o1.w = (v1.w - mean) * inv * g1.w + b1.w;
    float* op = out + (size_t)row * Dd + lane * 8;
    *(float4*)op       = o0;
    *(float4*)(op + 4) = o1;
    uint4 hv;
    hv.x = h2u(__floats2half2_rn(o0.x, o0.y));
    hv.y = h2u(__floats2half2_rn(o0.z, o0.w));
    hv.z = h2u(__floats2half2_rn(o1.x, o1.y));
    hv.w = h2u(__floats2half2_rn(o1.z, o1.w));
    *(uint4*)(outh + (size_t)row * Dd + lane * 8) = hv;
}

__global__ __launch_bounds__(256) void ln1_kernel(const float* __restrict__ x,
                                                  const float* __restrict__ g1,
                                                  const float* __restrict__ be1)
{ ln_body(x, g1, be1, g_h, g_hh); }

__global__ __launch_bounds__(256) void ln2_kernel(const float* __restrict__ g2,
                                                  const float* __restrict__ be2)
{ ln_body(g_hres, g2, be2, g_h2, g_h2h); }

// ============================================================================
// fp16 mma GEMM, both operands fp16 in gmem: pure-copy staging (no cvt).
// C[M,NC] = A[M,K] @ Wh^T. CTA 128x128, 8 warps, warp tile 64x32, chunks of 32.
// EPI: 0 store f32; 1 +Cadd f32; 3 +bias+Cadd f32; 4 +bias,relu -> fp16.
// ============================================================================
template <int K, int NC, int EPI>
__device__ __forceinline__ void gemm_hh(const __half* __restrict__ A,
                                        const __half* __restrict__ Wh,
                                        const float* __restrict__ Cadd,
                                        const float* __restrict__ bias,
                                        void* __restrict__ Cout)
{
    constexpr int NCH = K / 32;
    __shared__ __half As[2][BUFH];
    __shared__ __half Bs[2][BUFH];
    constexpr uint32_t BUFBYTES = BUFH * 2;

    const int t    = threadIdx.x;
    const int lane = t & 31;
    const int wid  = t >> 5;
    const int gr   = lane >> 2;
    const int tig  = lane & 3;
    const int wm   = (wid & 1) * 64;
    const int wn   = (wid >> 1) * 32;

    const int bm = blockIdx.y * 128;
    const int bn = blockIdx.x * 128;

    const uint32_t a_base = smem_u32(As) +
        ((wm + (lane & 15)) * SPH + ((lane >> 4) & 1) * 8) * 2;
    const uint32_t b_base = smem_u32(Bs) +
        ((wn + (lane & 7)) * SPH + ((lane >> 3) & 1) * 8) * 2;

    const int lrow = t >> 1;
    const int lko  = (t & 1) * 16;
    const uint4* Agh = (const uint4*)(A  + (size_t)(bm + lrow) * K);
    const uint4* Bgh = (const uint4*)(Wh + (size_t)(bn + lrow) * K);
    const int    gi  = (t & 1) * 2;   // uint4 index base; + c*4 per chunk

    uint4 pa0, pa1, pb0, pb1;
    pa0 = Agh[gi];     pa1 = Agh[gi + 1];
    pb0 = Bgh[gi];     pb1 = Bgh[gi + 1];

    float acc[4][4][4];
#pragma unroll
    for (int im = 0; im < 4; im++)
#pragma unroll
        for (int in = 0; in < 4; in++)
#pragma unroll
            for (int j = 0; j < 4; j++) acc[im][in][j] = 0.f;

    {
        __half* asw = &As[0][lrow * SPH + lko];
        *(uint4*)asw       = pa0;
        *(uint4*)(asw + 8) = pa1;
        __half* bsw = &Bs[0][lrow * SPH + lko];
        *(uint4*)bsw       = pb0;
        *(uint4*)(bsw + 8) = pb1;
    }
    __syncthreads();

    for (int c = 0; c < NCH; c++) {
        const int buf = c & 1;

        if (c + 1 < NCH) {
            pa0 = Agh[gi + (c + 1) * 4];
            pa1 = Agh[gi + (c + 1) * 4 + 1];
            pb0 = Bgh[gi + (c + 1) * 4];
            pb1 = Bgh[gi + (c + 1) * 4 + 1];
        }

        const uint32_t a_addr = a_base + buf * BUFBYTES;
        const uint32_t b_addr = b_base + buf * BUFBYTES;
#pragma unroll
        for (int ks = 0; ks < 2; ks++) {
            uint32_t af[4][4], bf[4][2];
#pragma unroll
            for (int im = 0; im < 4; im++)
                ldsm_x4(af[im], a_addr + (uint32_t)(im * 16 * SPH * 2 + ks * 32));
#pragma unroll
            for (int in = 0; in < 4; in++)
                ldsm_x2(bf[in], b_addr + (uint32_t)(in * 8 * SPH * 2 + ks * 32));
#pragma unroll
            for (int im = 0; im < 4; im++)
#pragma unroll
                for (int in = 0; in < 4; in++)
                    mma_f16(acc[im][in], af[im][0], af[im][1], af[im][2], af[im][3],
                            bf[in][0], bf[in][1]);
        }

        if (c + 1 < NCH) {
            const int nb = buf ^ 1;
            __half* asw = &As[nb][lrow * SPH + lko];
            *(uint4*)asw       = pa0;
            *(uint4*)(asw + 8) = pa1;
            __half* bsw = &Bs[nb][lrow * SPH + lko];
            *(uint4*)bsw       = pb0;
            *(uint4*)(bsw + 8) = pb1;
            __syncthreads();
        }
    }

    // epilogue
#pragma unroll
    for (int im = 0; im < 4; im++) {
        const int r0 = bm + wm + im * 16 + gr;
#pragma unroll
        for (int in = 0; in < 4; in++) {
            const int col = bn + wn + in * 8 + 2 * tig;
            float2 v0 = make_float2(acc[im][in][0], acc[im][in][1]);
            float2 v1 = make_float2(acc[im][in][2], acc[im][in][3]);
            if (EPI == 3 || EPI == 4) {
                const float2 bb = *(const float2*)&bias[col];
                v0.x += bb.x; v0.y += bb.y;
                v1.x += bb.x; v1.y += bb.y;
            }
            if (EPI == 4) {
                v0.x = fmaxf(v0.x, 0.f); v0.y = fmaxf(v0.y, 0.f);
                v1.x = fmaxf(v1.x, 0.f); v1.y = fmaxf(v1.y, 0.f);
            }
            if (EPI == 1 || EPI == 3) {
                const float2 c0 = *(const float2*)&Cadd[(size_t)r0 * NC + col];
                const float2 c1 = *(const float2*)&Cadd[(size_t)(r0 + 8) * NC + col];
                v0.x += c0.x; v0.y += c0.y;
                v1.x += c1.x; v1.y += c1.y;
            }
            if (EPI == 4) {
                __half* Ch = (__half*)Cout;
                *(uint32_t*)&Ch[(size_t)r0 * NC + col] =
                    h2u(__floats2half2_rn(v0.x, v0.y));
                *(uint32_t*)&Ch[(size_t)(r0 + 8) * NC + col] =
                    h2u(__floats2half2_rn(v1.x, v1.y));
            } else {
                float* Cf = (float*)Cout;
                *(float2*)&Cf[(size_t)r0 * NC + col]       = v0;
                *(float2*)&Cf[(size_t)(r0 + 8) * NC + col] = v1;
            }
        }
    }
}

__global__ __launch_bounds__(256, 2) void k_proj_tc()
{ gemm_hh<Dd, DFF, 0>(g_hh, g_Wh_qkv, nullptr, nullptr, g_proj); }

__global__ __launch_bounds__(256, 2) void k_wo_tc()
{ gemm_hh<Dd, Dd, 1>(g_att, g_Wh_o, g_h, nullptr, g_hres); }

__global__ __launch_bounds__(256, 2) void k_ffn1_tc(const float* __restrict__ b1)
{ gemm_hh<Dd, DFF, 4>(g_h2h, g_Wh_1, nullptr, b1, g_ffn); }

__global__ __launch_bounds__(256, 2) void k_ffn2_tc(const float* __restrict__ b2,
                                                    float* __restrict__ out)
{ gemm_hh<DFF, Dd, 3>(g_ffn, g_Wh_2, g_h2, b2, out); }

// ============================================================================
// Triangle attention v9 — TX=8, y-split (32 rows/CTA, 128 thr, 256 CTAs),
// SMEM double-buffered, f32x2 math, no-max softmax; fp16 output stores.
// ============================================================================
__global__ __launch_bounds__(128) void attn9_kernel()
{
    const int bx = blockIdx.x;       // 0..15
    const int xt = bx >> 1;          // 0..7
    const int yh = bx & 1;           // y-half
    const int hh = blockIdx.y;
    const int b  = blockIdx.z;
    const int t  = threadIdx.x;      // 0..127
    const int yl = t >> 2;           // local y 0..31
    const int dq = t & 3;
    const int x0 = xt * TX;
    const int y0 = yh * 32;
    const int y  = y0 + yl;

    __shared__ float rk_s[2][32][36];
    __shared__ float rv_s[2][32][36];
    __shared__ float lk_s[2][TX][36];
    __shared__ float lv_s[2][TX][36];

    const int r0c = t >> 3;          // 0..15
    const int r1c = r0c + 16;
    const int c4  = (t & 7) * 4;
    const int xr  = t >> 3;          // 0..7 (t<64)
    const int lc4 = c4;

    float4 prk0, prk1, prv0, prv1, plk, plv;
    u64 pmN, pmC;

    // ---- prefetch a = 0 ----
    {
        const int baseR = (b * Nn * Nn) * DFF + hh * DKk;
        prk0 = *(const float4*)&g_proj[baseR + (y0 + r0c) * DFF + 256 + c4];
        prv0 = *(const float4*)&g_proj[baseR + (y0 + r0c) * DFF + 768 + c4];
        prk1 = *(const float4*)&g_proj[baseR + (y0 + r1c) * DFF + 256 + c4];
        prv1 = *(const float4*)&g_proj[baseR + (y0 + r1c) * DFF + 768 + c4];
        if (t < 64) {
            const int baseL = ((b * Nn + x0 + xr) * Nn) * DFF + hh * DKk;
            plk = *(const float4*)&g_proj[baseL + lc4];
            plv = *(const float4*)&g_proj[baseL + 512 + lc4];
        }
        pmN = *(const u64*)&g_maskT[((b * Nn) * Nn + y) * 64 + x0];
    }
    *(float4*)&rk_s[0][r0c][c4] = prk0;
    *(float4*)&rv_s[0][r0c][c4] = prv0;
    *(float4*)&rk_s[0][r1c][c4] = prk1;
    *(float4*)&rv_s[0][r1c][c4] = prv1;
    if (t < 64) {
        *(float4*)&lk_s[0][xr][lc4] = plk;
        *(float4*)&lv_s[0][xr][lc4] = plv;
    }
    __syncthreads();

    u64 acc[TX][4];
    float l[TX];
#pragma unroll
    for (int xx = 0; xx < TX; xx++) {
        l[xx] = 0.f;
#pragma unroll
        for (int j = 0; j < 4; j++) acc[xx][j] = 0ull;
    }

    for (int a = 0; a < Nn; a++) {
        const int buf = a & 1;

        pmC = pmN;
        if (a + 1 < Nn) {   // prefetch a+1 (overlaps compute)
            const int baseR = ((b * Nn + (a + 1)) * Nn) * DFF + hh * DKk;
            prk0 = *(const float4*)&g_proj[baseR + (y0 + r0c) * DFF + 256 + c4];
            prv0 = *(const float4*)&g_proj[baseR + (y0 + r0c) * DFF + 768 + c4];
            prk1 = *(const float4*)&g_proj[baseR + (y0 + r1c) * DFF + 256 + c4];
            prv1 = *(const float4*)&g_proj[baseR + (y0 + r1c) * DFF + 768 + c4];
            if (t < 64) {
                const int baseL = ((b * Nn + x0 + xr) * Nn + (a + 1)) * DFF + hh * DKk;
                plk = *(const float4*)&g_proj[baseL + lc4];
                plv = *(const float4*)&g_proj[baseL + 512 + lc4];
            }
            pmN = *(const u64*)&g_maskT[((b * Nn + (a + 1)) * Nn + y) * 64 + x0];
        }

        // ---- compute step a ----
        const ulonglong2 rka = *(const ulonglong2*)&rk_s[buf][yl][dq * 8];
        const ulonglong2 rkb = *(const ulonglong2*)&rk_s[buf][yl][dq * 8 + 4];
        const ulonglong2 rva = *(const ulonglong2*)&rv_s[buf][yl][dq * 8];
        const ulonglong2 rvb = *(const ulonglong2*)&rv_s[buf][yl][dq * 8 + 4];

#pragma unroll
        for (int xx = 0; xx < TX; xx++) {
            const ulonglong2 lka = *(const ulonglong2*)&lk_s[buf][xx][dq * 8];
            const ulonglong2 lkb = *(const ulonglong2*)&lk_s[buf][xx][dq * 8 + 4];
            u64 s2 = mul2(lka.x, rka.x);
            s2 = fma2(lka.y, rka.y, s2);
            s2 = fma2(lkb.x, rkb.x, s2);
            s2 = fma2(lkb.y, rkb.y, s2);
            float lo, hi;
            upk2(s2, lo, hi);
            float part = lo + hi;
            part += __shfl_xor_sync(0xffffffffu, part, 1);
            part += __shfl_xor_sync(0xffffffffu, part, 2);
            const float sc = ((pmC >> (xx * 8)) & 0xffull) ? -1e9f : part;
            const float p  = __expf(sc);
            l[xx] += p;
            const u64 pp = pk2(p, p);
            const ulonglong2 lva = *(const ulonglong2*)&lv_s[buf][xx][dq * 8];
            const ulonglong2 lvb = *(const ulonglong2*)&lv_s[buf][xx][dq * 8 + 4];
            acc[xx][0] = fma2(mul2(lva.x, rva.x), pp, acc[xx][0]);
            acc[xx][1] = fma2(mul2(lva.y, rva.y), pp, acc[xx][1]);
            acc[xx][2] = fma2(mul2(lvb.x, rvb.x), pp, acc[xx][2]);
            acc[xx][3] = fma2(mul2(lvb.y, rvb.y), pp, acc[xx][3]);
        }

        // ---- store prefetched a+1 into the other buffer ----
        if (a + 1 < Nn) {
            const int nb = buf ^ 1;
            *(float4*)&rk_s[nb][r0c][c4] = prk0;
            *(float4*)&rv_s[nb][r0c][c4] = prv0;
            *(float4*)&rk_s[nb][r1c][c4] = prk1;
            *(float4*)&rv_s[nb][r1c][c4] = prv1;
            if (t < 64) {
                *(float4*)&lk_s[nb][xr][lc4] = plk;
                *(float4*)&lv_s[nb][xr][lc4] = plv;
            }
            __syncthreads();
        }
    }

#pragma unroll
    for (int xx = 0; xx < TX; xx++) {
        const float inv = 1.0f / l[xx];
        const int ob = ((b * Nn + x0 + xx) * Nn + y) * Dd + hh * DKk + dq * 8;
        float a0, a1, a2, a3, a4, a5, a6, a7;
        upk2(acc[xx][0], a0, a1);
        upk2(acc[xx][1], a2, a3);
        upk2(acc[xx][2], a4, a5);
        upk2(acc[xx][3], a6, a7);
        uint4 hv;
        hv.x = h2u(__floats2half2_rn(a0 * inv, a1 * inv));
        hv.y = h2u(__floats2half2_rn(a2 * inv, a3 * inv));
        hv.z = h2u(__floats2half2_rn(a4 * inv, a5 * inv));
        hv.w = h2u(__floats2half2_rn(a6 * inv, a7 * inv));
        *(uint4*)&g_att[ob] = hv;
    }
}

// ============================================================================
// launch
// ============================================================================
extern "C" void kernel_launch(void* const* d_in, const int* in_sizes, int n_in,
                              void* d_out, int out_size)
{
    const float*         x    = (const float*)d_in[0];
    const unsigned char* mask = (const unsigned char*)d_in[1];
    const float*         Wlk  = (const float*)d_in[2];
    const float*         Wrk  = (const float*)d_in[3];
    const float*         Wlv  = (const float*)d_in[4];
    const float*         Wrv  = (const float*)d_in[5];
    const float*         Wo   = (const float*)d_in[6];
    const float*         W1   = (const float*)d_in[7];
    const float*         b1   = (const float*)d_in[8];
    const float*         W2   = (const float*)d_in[9];
    const float*         b2   = (const float*)d_in[10];
    const float*         g1   = (const float*)d_in[11];
    const float*         be1  = (const float*)d_in[12];
    const float*         g2   = (const float*)d_in[13];
    const float*         be2  = (const float*)d_in[14];
    float* out = (float*)d_out;

    k_prep<<<2880, 256>>>(Wlk, Wrk, Wlv, Wrv, Wo, W1, W2, mask);
    ln1_kernel<<<RR / 8, 256>>>(x, g1, be1);
    k_proj_tc<<<dim3(DFF / 128, RR / 128), 256>>>();
    attn9_kernel<<<dim3(16, Hh, Bb), 128>>>();
    k_wo_tc<<<dim3(Dd / 128, RR / 128), 256>>>();
    ln2_kernel<<<RR / 8, 256>>>(g2, be2);
    k_ffn1_tc<<<dim3(DFF / 128, RR / 128), 256>>>(b1);
    k_ffn2_tc<<<dim3(Dd / 128, RR / 128), 256>>>(b2, out);
}